// round 11
// baseline (speedup 1.0000x reference)
#include <cuda_runtime.h>

// ---------------------------------------------------------------------------
// DisenHAN on GB300 — fp32, restructured.
// Key identity: with one neighbor type, beta = softmax over a singleton = 1,
// so wp stays ones and routing is plain per-facet softmax attention, iterated 3x.
// Pre-transform: TU = user_table @ Wpre1_user, TI = item_table @ Wpre1_item
// serve BOTH branches' layer-1 neighbor AND center transforms via gather.
// ---------------------------------------------------------------------------

#define VCAP   100000
#define NB     2048          // batch
#define NS     16            // hop-1 fanout (N0)
#define NN     16            // hop-2 fanout (N1)

#define OFF_TU  0L
#define OFF_TI  ((long)VCAP * 64)
#define OFF_H1  ((long)2 * VCAP * 64)                       // [2][32768][64]
#define OFF_H1T (OFF_H1 + (long)2 * NB * NS * 64)           // [2][32768][64]
#define SCRATCH_FLOATS (OFF_H1T + (long)2 * NB * NS * 64)

__device__ float g_scratch[SCRATCH_FLOATS];

// ---------------------------------------------------------------------------
// O[M,64] = A[M,64] @ W[64,64].  A is external (Aext) or scratch+aoff.
// 128 rows/block, 256 threads, each thread computes an 8x4 output tile.
// FFMA-bound by design (per d: 1 LDS.128 + 8 broadcast LDS + 32 FFMA).
// ---------------------------------------------------------------------------
__global__ __launch_bounds__(256) void gemm64(const float* __restrict__ Aext, long aoff,
                                              const float* __restrict__ W,
                                              long ooff, int M) {
    __shared__ float sW[64 * 64];
    __shared__ float sX[128 * 64];
    const float* __restrict__ A = Aext ? Aext : (g_scratch + aoff);
    float* __restrict__ O = g_scratch + ooff;
    const int tid  = threadIdx.x;
    const int row0 = blockIdx.x * 128;

    // Load W (4096 floats) straight into smem
    {
        const float4* W4 = (const float4*)W;
        float4* sW4 = (float4*)sW;
#pragma unroll
        for (int i = 0; i < 4; i++) sW4[tid + 256 * i] = W4[tid + 256 * i];
    }
    // Load 128x64 A tile (coalesced float4), zero-fill past M
    {
        float4* sX4 = (float4*)sX;
#pragma unroll
        for (int i = 0; i < 8; i++) {
            int f4 = tid + 256 * i;          // 0..2047
            int r  = f4 >> 4;
            int c4 = f4 & 15;
            float4 v = make_float4(0.f, 0.f, 0.f, 0.f);
            int gr = row0 + r;
            if (gr < M) v = __ldg(((const float4*)A) + (long)gr * 16 + c4);
            sX4[f4] = v;
        }
    }
    __syncthreads();

    const int cg = tid & 15;   // 4-col group
    const int rg = tid >> 4;   // 8-row group
    float acc[8][4];
#pragma unroll
    for (int i = 0; i < 8; i++) {
        acc[i][0] = 0.f; acc[i][1] = 0.f; acc[i][2] = 0.f; acc[i][3] = 0.f;
    }
#pragma unroll 16
    for (int d = 0; d < 64; d++) {
        float4 w = *(const float4*)&sW[d * 64 + 4 * cg];
#pragma unroll
        for (int i = 0; i < 8; i++) {
            float a = sX[(8 * rg + i) * 64 + d];     // broadcast within half-warp
            acc[i][0] = fmaf(a, w.x, acc[i][0]);
            acc[i][1] = fmaf(a, w.y, acc[i][1]);
            acc[i][2] = fmaf(a, w.z, acc[i][2]);
            acc[i][3] = fmaf(a, w.w, acc[i][3]);
        }
    }
#pragma unroll
    for (int i = 0; i < 8; i++) {
        int gr = row0 + 8 * rg + i;
        if (gr < M)
            *(float4*)&O[(long)gr * 64 + 4 * cg] =
                make_float4(acc[i][0], acc[i][1], acc[i][2], acc[i][3]);
    }
}

// ---------------------------------------------------------------------------
// Routing core (warp-level). 8 facets x 8 dims; lane = (facet k = lane>>2,
// sub = lane&3). Each lane owns the FULL 8-dim facet slice of 4 neighbors
// (n = 4*sub + j) -> dot products need no shuffles. softmax stats and the
// z aggregate reduce across the 4-lane facet group via shfl_xor 1,2.
//   3 iterations of: e = ct.nh/sqrt(8); a = softmax_n e; ht = c + a.nh
// ---------------------------------------------------------------------------
__device__ __forceinline__ void routing_core(const float cf[8], const float nhf[4][8],
                                             float ht[8]) {
    const float CS = 1.4426950408889634f * 0.35355339059327373f;  // log2(e)/sqrt(8)
#pragma unroll
    for (int it = 0; it < 3; it++) {
        float l[4];
#pragma unroll
        for (int j = 0; j < 4; j++) {
            float p = ht[0] * nhf[j][0];
#pragma unroll
            for (int d = 1; d < 8; d++) p = fmaf(ht[d], nhf[j][d], p);
            l[j] = p * CS;   // base-2 logits
        }
        float m = fmaxf(fmaxf(l[0], l[1]), fmaxf(l[2], l[3]));
        m = fmaxf(m, __shfl_xor_sync(0xffffffffu, m, 1));
        m = fmaxf(m, __shfl_xor_sync(0xffffffffu, m, 2));
        float a[4], s = 0.f;
#pragma unroll
        for (int j = 0; j < 4; j++) { a[j] = exp2f(l[j] - m); s += a[j]; }
        s += __shfl_xor_sync(0xffffffffu, s, 1);
        s += __shfl_xor_sync(0xffffffffu, s, 2);
        float inv = __fdividef(1.f, s);
        float z[8];
#pragma unroll
        for (int d = 0; d < 8; d++) z[d] = a[0] * nhf[0][d];
#pragma unroll
        for (int j = 1; j < 4; j++)
#pragma unroll
            for (int d = 0; d < 8; d++) z[d] = fmaf(a[j], nhf[j][d], z[d]);
#pragma unroll
        for (int d = 0; d < 8; d++) {
            z[d] += __shfl_xor_sync(0xffffffffu, z[d], 1);
            z[d] += __shfl_xor_sync(0xffffffffu, z[d], 2);
            ht[d] = fmaf(z[d], inv, cf[d]);
        }
    }
}

__device__ __forceinline__ void load8(const float* __restrict__ p, float v[8]) {
    float4 t0 = __ldg((const float4*)p);
    float4 t1 = __ldg((const float4*)(p + 4));
    v[0] = t0.x; v[1] = t0.y; v[2] = t0.z; v[3] = t0.w;
    v[4] = t1.x; v[5] = t1.y; v[6] = t1.z; v[7] = t1.w;
}

// Select this lane's 2 output dims (dims 2*lane = 8k+2sub) without dynamic
// register indexing.
__device__ __forceinline__ float2 pick2(const float ht[8], int sub) {
    float2 o;
    o.x = (sub == 0) ? ht[0] : (sub == 1) ? ht[2] : (sub == 2) ? ht[4] : ht[6];
    o.y = (sub == 0) ? ht[1] : (sub == 1) ? ht[3] : (sub == 2) ? ht[5] : ht[7];
    return o;
}

// ---------------------------------------------------------------------------
// Layer 1: one warp per (branch, b, s) site. 65536 warps.
// user branch: center = TI[user_idx1], neighbors = TU[user_idx2]
// item branch: center = TU[item_idx1], neighbors = TI[item_idx2]
// relu at the end; writes h1.
// ---------------------------------------------------------------------------
__global__ __launch_bounds__(256) void routing_l1(const int* __restrict__ uidx1,
                                                  const int* __restrict__ uidx2,
                                                  const int* __restrict__ iidx1,
                                                  const int* __restrict__ iidx2) {
    int w    = blockIdx.x * 8 + (threadIdx.x >> 5);
    int lane = threadIdx.x & 31;
    int branch = w >> 15;           // 0=user, 1=item
    int site   = w & 32767;         // b*16 + s
    const float* cT; const float* nT; const int* i1p; const int* i2p;
    if (branch == 0) { cT = g_scratch + OFF_TI; nT = g_scratch + OFF_TU; i1p = uidx1; i2p = uidx2; }
    else             { cT = g_scratch + OFF_TU; nT = g_scratch + OFF_TI; i1p = iidx1; i2p = iidx2; }
    int k = lane >> 2, sub = lane & 3;

    float cf[8], ht[8], nhf[4][8];
    {
        long cb = (long)__ldg(&i1p[site]) * 64 + 8 * k;
        load8(cT + cb, cf);
    }
#pragma unroll
    for (int j = 0; j < 4; j++) {
        long rb = (long)__ldg(&i2p[site * 16 + 4 * sub + j]) * 64 + 8 * k;
        load8(nT + rb, nhf[j]);
    }
#pragma unroll
    for (int d = 0; d < 8; d++) ht[d] = cf[d];

    routing_core(cf, nhf, ht);

#pragma unroll
    for (int d = 0; d < 8; d++) ht[d] = fmaxf(ht[d], 0.f);   // relu (layer 1)
    float2 o = pick2(ht, sub);
    *(float2*)&g_scratch[OFF_H1 + ((long)branch * (NB * NS) + site) * 64 + 2 * lane] = o;
}

// ---------------------------------------------------------------------------
// Layer 0: one warp per (branch, b). 4096 warps.
// center = raw table row (W_center = None); neighbors = h1t rows (contiguous).
// No relu; writes d_out: user_h [0..131071], item_h [131072..262143].
// ---------------------------------------------------------------------------
__global__ __launch_bounds__(256) void routing_l0(const float* __restrict__ user_table,
                                                  const float* __restrict__ item_table,
                                                  const int* __restrict__ uidx0,
                                                  const int* __restrict__ iidx0,
                                                  float* __restrict__ out) {
    int w    = blockIdx.x * 8 + (threadIdx.x >> 5);
    int lane = threadIdx.x & 31;
    int branch = w >> 11;          // 0=user, 1=item
    int b      = w & 2047;
    const float* tab = branch ? item_table : user_table;
    const int*   i0p = branch ? iidx0 : uidx0;
    int k = lane >> 2, sub = lane & 3;

    float cf[8], ht[8], nhf[4][8];
    {
        long cb = (long)__ldg(&i0p[b]) * 64 + 8 * k;
        load8(tab + cb, cf);
    }
    const float* nbase = g_scratch + OFF_H1T + ((long)branch * (NB * NS) + (long)b * NS) * 64;
#pragma unroll
    for (int j = 0; j < 4; j++) {
        load8(nbase + (4 * sub + j) * 64 + 8 * k, nhf[j]);
    }
#pragma unroll
    for (int d = 0; d < 8; d++) ht[d] = cf[d];

    routing_core(cf, nhf, ht);

    float2 o = pick2(ht, sub);
    *(float2*)&out[((long)branch * NB + b) * 64 + 2 * lane] = o;
}

// ---------------------------------------------------------------------------
// Inputs (metadata order):
//  0 user_table[V,64] 1 item_table[V,64]
//  2 Wpre0_user 3 Wpre0_item 4 Wpre1_user 5 Wpre1_item      (all [64,64] f32)
//  6 user_idx0[B] 7 user_idx1[B,16] 8 user_idx2[B,16,16]    (int32)
//  9 item_idx0    10 item_idx1      11 item_idx2
// Output: f32 [2,2048,64] = (user_h, item_h)
// ---------------------------------------------------------------------------
extern "C" void kernel_launch(void* const* d_in, const int* in_sizes, int n_in,
                              void* d_out, int out_size) {
    const float* user_table = (const float*)d_in[0];
    const float* item_table = (const float*)d_in[1];
    const float* W0u = (const float*)d_in[2];
    const float* W0i = (const float*)d_in[3];
    const float* W1u = (const float*)d_in[4];
    const float* W1i = (const float*)d_in[5];
    const int* u0 = (const int*)d_in[6];
    const int* u1 = (const int*)d_in[7];
    const int* u2 = (const int*)d_in[8];
    const int* i0 = (const int*)d_in[9];
    const int* i1 = (const int*)d_in[10];
    const int* i2 = (const int*)d_in[11];

    const int V  = in_sizes[0] / 64;           // 100000
    const int gb = (V + 127) / 128;

    // 1-2: pre-transform both tables (serve layer-1 centers AND neighbors of both branches)
    gemm64<<<gb, 256>>>(user_table, 0L, W1u, OFF_TU, V);
    gemm64<<<gb, 256>>>(item_table, 0L, W1i, OFF_TI, V);

    // 3: layer-1 routing (2 * 2048 * 16 sites, one warp each)
    routing_l1<<<(2 * NB * NS) / 8, 256>>>(u1, u2, i1, i2);

    // 4-5: layer-0 neighbor transform h1 @ W0n (user branch uses Wpre0_item, item uses Wpre0_user)
    const long H1SZ = (long)NB * NS * 64;
    gemm64<<<(NB * NS) / 128, 256>>>(nullptr, OFF_H1,        W0i, OFF_H1T,        NB * NS);
    gemm64<<<(NB * NS) / 128, 256>>>(nullptr, OFF_H1 + H1SZ, W0u, OFF_H1T + H1SZ, NB * NS);

    // 6: layer-0 routing -> output
    routing_l0<<<(2 * NB) / 8, 256>>>(user_table, item_table, u0, i0, (float*)d_out);
    (void)n_in; (void)out_size;
}

// round 16
// speedup vs baseline: 1.0394x; 1.0394x over previous
#include <cuda_runtime.h>

// ---------------------------------------------------------------------------
// DisenHAN on GB300 — fp32, restructured, FFMA2 GEMMs.
// Identity: with one neighbor type, the hete softmax is over a singleton
// => beta == 1 => wp stays ones; routing = 3 iterations of plain per-facet
// softmax attention. Pre-transform TU = user_table@Wpre1_user and
// TI = item_table@Wpre1_item; they serve both branches' layer-1 center AND
// neighbor transforms via gather.
// GEMMs use packed fp32x2 FMA (fma.rn.f32x2) with a d-parity accumulator
// split: acc.lo sums even-d terms, acc.hi odd-d terms, combined at the end.
// ---------------------------------------------------------------------------

#define VCAP   100000
#define NB     2048          // batch
#define NS     16            // hop-1 fanout (N0)
#define NN     16            // hop-2 fanout (N1)

#define OFF_TU  0L
#define OFF_TI  ((long)VCAP * 64)
#define OFF_H1  ((long)2 * VCAP * 64)                       // [2][32768][64]
#define OFF_H1T (OFF_H1 + (long)2 * NB * NS * 64)           // [2][32768][64]
#define SCRATCH_FLOATS (OFF_H1T + (long)2 * NB * NS * 64)

__device__ float g_scratch[SCRATCH_FLOATS];

typedef unsigned long long ull;

__device__ __forceinline__ ull ffma2(ull a, ull b, ull c) {
    ull d;
    asm("fma.rn.f32x2 %0, %1, %2, %3;" : "=l"(d) : "l"(a), "l"(b), "l"(c));
    return d;
}
__device__ __forceinline__ float pairsum(ull x) {
    float lo = __uint_as_float((unsigned)(x & 0xffffffffu));
    float hi = __uint_as_float((unsigned)(x >> 32));
    return lo + hi;
}

// ---------------------------------------------------------------------------
// Two independent O[M,64] = A[M,64] @ W[64,64] problems in one launch.
// Blocks [0, bph) do problem 0; [bph, 2*bph) do problem 1.
// 128 rows/block, 256 threads, 8x4 output tile/thread, fp32x2 FMA.
// W staged transposed + XOR-swizzled in smem:
//   sWT2[c*32 + (dp ^ (c>>2))] = {W[2dp][c], W[2dp+1][c]}  (as float2)
// ---------------------------------------------------------------------------
__global__ __launch_bounds__(256) void gemm64x2(
        const float* __restrict__ A0, const float* __restrict__ A1,
        long a0off, long a1off,
        const float* __restrict__ Wp0, const float* __restrict__ Wp1,
        long o0off, long o1off, int M, int bph) {
    __shared__ float sWT[64 * 64];
    __shared__ float sX[128 * 64];

    const int tid = threadIdx.x;
    const bool second = (int)blockIdx.x >= bph;
    const float* __restrict__ W    = second ? Wp1 : Wp0;
    const float* __restrict__ Aext = second ? A1 : A0;
    const long aoff = second ? a1off : a0off;
    const long ooff = second ? o1off : o0off;
    const int  row0 = (second ? (int)blockIdx.x - bph : (int)blockIdx.x) * 128;
    const float* __restrict__ A = Aext ? Aext : (g_scratch + aoff);
    float* __restrict__ O = g_scratch + ooff;

    // Stage W transposed + swizzled (coalesced global reads).
#pragma unroll
    for (int e = tid; e < 2048; e += 256) {
        int dp = e >> 6;     // d-pair 0..31
        int c  = e & 63;     // output column
        float w0 = __ldg(&W[(2 * dp) * 64 + c]);
        float w1 = __ldg(&W[(2 * dp) * 64 + 64 + c]);
        int idx = c * 32 + (dp ^ (c >> 2));
        sWT[2 * idx]     = w0;
        sWT[2 * idx + 1] = w1;
    }
    // Load 128x64 A tile (coalesced float4), zero-fill past M.
    {
        float4* sX4 = (float4*)sX;
#pragma unroll
        for (int i = 0; i < 8; i++) {
            int f4 = tid + 256 * i;          // 0..2047
            int r  = f4 >> 4;
            int c4 = f4 & 15;
            float4 v = make_float4(0.f, 0.f, 0.f, 0.f);
            int gr = row0 + r;
            if (gr < M) v = __ldg(((const float4*)A) + (long)gr * 16 + c4);
            sX4[f4] = v;
        }
    }
    __syncthreads();

    const int cg = tid & 15;   // 4-column group
    const int rg = tid >> 4;   // 8-row group
    ull acc[8][4];
#pragma unroll
    for (int i = 0; i < 8; i++)
#pragma unroll
        for (int c = 0; c < 4; c++) acc[i][c] = 0ULL;

    const ull* __restrict__ sWu = (const ull*)sWT + 128 * cg;  // (4cg)*32
    const float* __restrict__ xrow = sX + (8 * rg) * 64;

#pragma unroll 8
    for (int dp = 0; dp < 32; dp++) {
        int sw = dp ^ cg;
        ull w0 = sWu[sw];
        ull w1 = sWu[32 + sw];
        ull w2 = sWu[64 + sw];
        ull w3 = sWu[96 + sw];
#pragma unroll
        for (int i = 0; i < 8; i++) {
            ull a2 = *(const ull*)&xrow[i * 64 + 2 * dp];
            acc[i][0] = ffma2(a2, w0, acc[i][0]);
            acc[i][1] = ffma2(a2, w1, acc[i][1]);
            acc[i][2] = ffma2(a2, w2, acc[i][2]);
            acc[i][3] = ffma2(a2, w3, acc[i][3]);
        }
    }

#pragma unroll
    for (int i = 0; i < 8; i++) {
        int gr = row0 + 8 * rg + i;
        if (gr < M) {
            float4 v;
            v.x = pairsum(acc[i][0]);
            v.y = pairsum(acc[i][1]);
            v.z = pairsum(acc[i][2]);
            v.w = pairsum(acc[i][3]);
            *(float4*)&O[(long)gr * 64 + 4 * cg] = v;
        }
    }
}

// ---------------------------------------------------------------------------
// Routing core (warp-level). 8 facets x 8 dims; lane = (facet k = lane>>2,
// sub = lane&3). Each lane owns the FULL 8-dim facet slice of 4 neighbors
// (n = 4*sub + j) -> dot products need no shuffles. softmax stats and the
// z aggregate reduce across the 4-lane facet group via shfl_xor 1,2.
//   3 iterations of: e = ct.nh/sqrt(8); a = softmax_n e; ht = c + a.nh
// ---------------------------------------------------------------------------
__device__ __forceinline__ void routing_core(const float cf[8], const float nhf[4][8],
                                             float ht[8]) {
    const float CS = 1.4426950408889634f * 0.35355339059327373f;  // log2(e)/sqrt(8)
#pragma unroll
    for (int it = 0; it < 3; it++) {
        float l[4];
#pragma unroll
        for (int j = 0; j < 4; j++) {
            float p = ht[0] * nhf[j][0];
#pragma unroll
            for (int d = 1; d < 8; d++) p = fmaf(ht[d], nhf[j][d], p);
            l[j] = p * CS;   // base-2 logits
        }
        float m = fmaxf(fmaxf(l[0], l[1]), fmaxf(l[2], l[3]));
        m = fmaxf(m, __shfl_xor_sync(0xffffffffu, m, 1));
        m = fmaxf(m, __shfl_xor_sync(0xffffffffu, m, 2));
        float a[4], s = 0.f;
#pragma unroll
        for (int j = 0; j < 4; j++) { a[j] = exp2f(l[j] - m); s += a[j]; }
        s += __shfl_xor_sync(0xffffffffu, s, 1);
        s += __shfl_xor_sync(0xffffffffu, s, 2);
        float inv = __fdividef(1.f, s);
        float z[8];
#pragma unroll
        for (int d = 0; d < 8; d++) z[d] = a[0] * nhf[0][d];
#pragma unroll
        for (int j = 1; j < 4; j++)
#pragma unroll
            for (int d = 0; d < 8; d++) z[d] = fmaf(a[j], nhf[j][d], z[d]);
#pragma unroll
        for (int d = 0; d < 8; d++) {
            z[d] += __shfl_xor_sync(0xffffffffu, z[d], 1);
            z[d] += __shfl_xor_sync(0xffffffffu, z[d], 2);
            ht[d] = fmaf(z[d], inv, cf[d]);
        }
    }
}

__device__ __forceinline__ void load8(const float* __restrict__ p, float v[8]) {
    float4 t0 = __ldg((const float4*)p);
    float4 t1 = __ldg((const float4*)(p + 4));
    v[0] = t0.x; v[1] = t0.y; v[2] = t0.z; v[3] = t0.w;
    v[4] = t1.x; v[5] = t1.y; v[6] = t1.z; v[7] = t1.w;
}

// Select this lane's 2 output dims (dims 2*lane = 8k+2sub) without dynamic
// register indexing.
__device__ __forceinline__ float2 pick2(const float ht[8], int sub) {
    float2 o;
    o.x = (sub == 0) ? ht[0] : (sub == 1) ? ht[2] : (sub == 2) ? ht[4] : ht[6];
    o.y = (sub == 0) ? ht[1] : (sub == 1) ? ht[3] : (sub == 2) ? ht[5] : ht[7];
    return o;
}

// ---------------------------------------------------------------------------
// Layer 1: one warp per (branch, b, s) site. 65536 warps.
// user branch: center = TI[user_idx1], neighbors = TU[user_idx2]
// item branch: center = TU[item_idx1], neighbors = TI[item_idx2]
// relu at the end; writes h1.
// ---------------------------------------------------------------------------
__global__ __launch_bounds__(256) void routing_l1(const int* __restrict__ uidx1,
                                                  const int* __restrict__ uidx2,
                                                  const int* __restrict__ iidx1,
                                                  const int* __restrict__ iidx2) {
    int w    = blockIdx.x * 8 + (threadIdx.x >> 5);
    int lane = threadIdx.x & 31;
    int branch = w >> 15;           // 0=user, 1=item
    int site   = w & 32767;         // b*16 + s
    const float* cT; const float* nT; const int* i1p; const int* i2p;
    if (branch == 0) { cT = g_scratch + OFF_TI; nT = g_scratch + OFF_TU; i1p = uidx1; i2p = uidx2; }
    else             { cT = g_scratch + OFF_TU; nT = g_scratch + OFF_TI; i1p = iidx1; i2p = iidx2; }
    int k = lane >> 2, sub = lane & 3;

    float cf[8], ht[8], nhf[4][8];
    {
        long cb = (long)__ldg(&i1p[site]) * 64 + 8 * k;
        load8(cT + cb, cf);
    }
#pragma unroll
    for (int j = 0; j < 4; j++) {
        long rb = (long)__ldg(&i2p[site * 16 + 4 * sub + j]) * 64 + 8 * k;
        load8(nT + rb, nhf[j]);
    }
#pragma unroll
    for (int d = 0; d < 8; d++) ht[d] = cf[d];

    routing_core(cf, nhf, ht);

#pragma unroll
    for (int d = 0; d < 8; d++) ht[d] = fmaxf(ht[d], 0.f);   // relu (layer 1)
    float2 o = pick2(ht, sub);
    *(float2*)&g_scratch[OFF_H1 + ((long)branch * (NB * NS) + site) * 64 + 2 * lane] = o;
}

// ---------------------------------------------------------------------------
// Layer 0: one warp per (branch, b). 4096 warps.
// center = raw table row (W_center = None); neighbors = h1t rows (contiguous).
// No relu; writes d_out: user_h [0..131071], item_h [131072..262143].
// ---------------------------------------------------------------------------
__global__ __launch_bounds__(256) void routing_l0(const float* __restrict__ user_table,
                                                  const float* __restrict__ item_table,
                                                  const int* __restrict__ uidx0,
                                                  const int* __restrict__ iidx0,
                                                  float* __restrict__ out) {
    int w    = blockIdx.x * 8 + (threadIdx.x >> 5);
    int lane = threadIdx.x & 31;
    int branch = w >> 11;          // 0=user, 1=item
    int b      = w & 2047;
    const float* tab = branch ? item_table : user_table;
    const int*   i0p = branch ? iidx0 : uidx0;
    int k = lane >> 2, sub = lane & 3;

    float cf[8], ht[8], nhf[4][8];
    {
        long cb = (long)__ldg(&i0p[b]) * 64 + 8 * k;
        load8(tab + cb, cf);
    }
    const float* nbase = g_scratch + OFF_H1T + ((long)branch * (NB * NS) + (long)b * NS) * 64;
#pragma unroll
    for (int j = 0; j < 4; j++) {
        load8(nbase + (4 * sub + j) * 64 + 8 * k, nhf[j]);
    }
#pragma unroll
    for (int d = 0; d < 8; d++) ht[d] = cf[d];

    routing_core(cf, nhf, ht);

    float2 o = pick2(ht, sub);
    *(float2*)&out[((long)branch * NB + b) * 64 + 2 * lane] = o;
}

// ---------------------------------------------------------------------------
// Inputs (metadata order):
//  0 user_table[V,64] 1 item_table[V,64]
//  2 Wpre0_user 3 Wpre0_item 4 Wpre1_user 5 Wpre1_item      (all [64,64] f32)
//  6 user_idx0[B] 7 user_idx1[B,16] 8 user_idx2[B,16,16]    (int32)
//  9 item_idx0    10 item_idx1      11 item_idx2
// Output: f32 [2,2048,64] = (user_h, item_h)
// ---------------------------------------------------------------------------
extern "C" void kernel_launch(void* const* d_in, const int* in_sizes, int n_in,
                              void* d_out, int out_size) {
    const float* user_table = (const float*)d_in[0];
    const float* item_table = (const float*)d_in[1];
    const float* W0u = (const float*)d_in[2];
    const float* W0i = (const float*)d_in[3];
    const float* W1u = (const float*)d_in[4];
    const float* W1i = (const float*)d_in[5];
    const int* u0 = (const int*)d_in[6];
    const int* u1 = (const int*)d_in[7];
    const int* u2 = (const int*)d_in[8];
    const int* i0 = (const int*)d_in[9];
    const int* i1 = (const int*)d_in[10];
    const int* i2 = (const int*)d_in[11];

    const int V   = in_sizes[0] / 64;           // 100000
    const int bph = (V + 127) / 128;            // 782

    // 1: pre-transform both tables in ONE launch
    //    TU = user_table @ W1u ; TI = item_table @ W1i
    gemm64x2<<<2 * bph, 256>>>(user_table, item_table, 0L, 0L,
                               W1u, W1i, OFF_TU, OFF_TI, V, bph);

    // 2: layer-1 routing (2 * 2048 * 16 sites, one warp each)
    routing_l1<<<(2 * NB * NS) / 8, 256>>>(u1, u2, i1, i2);

    // 3: layer-0 neighbor transform, both branches in ONE launch
    //    user branch: h1_u @ W0i ; item branch: h1_i @ W0u
    const long H1SZ = (long)NB * NS * 64;
    const int  bphS = (NB * NS) / 128;          // 256
    gemm64x2<<<2 * bphS, 256>>>(nullptr, nullptr, OFF_H1, OFF_H1 + H1SZ,
                                W0i, W0u, OFF_H1T, OFF_H1T + H1SZ,
                                NB * NS, bphS);

    // 4: layer-0 routing -> output
    routing_l0<<<(2 * NB) / 8, 256>>>(user_table, item_table, u0, i0, (float*)d_out);
    (void)n_in; (void)out_size;
}